// round 1
// baseline (speedup 1.0000x reference)
#include <cuda_runtime.h>
#include <cstdint>

// Problem dims (fixed by the dataset)
#define HH   256
#define WW   256
#define NWF  129                 // W/2+1
#define FREQ (HH*NWF)            // 33024 frequency bins
#define NB   16                  // batch
#define NC   32                  // in channels
#define NO   32                  // out channels

// Frequency-domain scratch (static device globals: allocation-free)
__device__ float2 g_Xf[NB*NC*FREQ];   // 135 MB
__device__ float2 g_Kf[NO*NC*FREQ];   // 270 MB
__device__ float2 g_Of[NB*NO*FREQ];   // 135 MB
__device__ float2 g_tw[256];          // forward twiddles e^{-2pi i k/256}

// ---------------------------------------------------------------------------
// Twiddle init (double precision, once per launch; trivially cheap)
// ---------------------------------------------------------------------------
__global__ void init_tw_kernel() {
    int k = threadIdx.x;
    double s, c;
    sincospi((double)k / 128.0, &s, &c);   // angle = 2*pi*k/256
    g_tw[k] = make_float2((float)c, (float)(-s));
}

// ---------------------------------------------------------------------------
// 256-point radix-2 DIT FFT in shared memory.
// d: base pointer (element i lives at d[i*stride]); nt threads cooperate,
// local thread id t in [0,nt). All threads of the block must call (syncs).
// INV=0: forward (e^{-}), INV=1: inverse without 1/N scaling (e^{+}).
// ---------------------------------------------------------------------------
template<int INV>
__device__ __forceinline__ void fft256(float2* d, int stride, int t, int nt,
                                       const float2* tw) {
    // bit-reverse permutation (disjoint pairs per thread)
    for (int i = t; i < 256; i += nt) {
        int j = (int)(__brev((unsigned)i) >> 24);
        if (j > i) {
            float2 a = d[i*stride];
            d[i*stride] = d[j*stride];
            d[j*stride] = a;
        }
    }
    __syncthreads();
    #pragma unroll
    for (int s = 1; s <= 8; s++) {
        const int half = 1 << (s - 1);
        for (int k = t; k < 128; k += nt) {
            const int pos = k & (half - 1);
            const int i0  = ((k >> (s - 1)) << s) + pos;
            const int i1  = i0 + half;
            float2 wv = tw[pos << (8 - s)];     // W_len^pos
            if (INV) wv.y = -wv.y;
            float2 u = d[i0*stride];
            float2 v = d[i1*stride];
            float2 vw = make_float2(v.x*wv.x - v.y*wv.y,
                                    v.x*wv.y + v.y*wv.x);
            d[i0*stride] = make_float2(u.x + vw.x, u.y + vw.y);
            d[i1*stride] = make_float2(u.x - vw.x, u.y - vw.y);
        }
        __syncthreads();
    }
}

// ---------------------------------------------------------------------------
// Forward real FFT along W, two rows packed per complex FFT.
// Input : real image rows (n, h, w), n = image index.
// Output: (n, h, wf) complex, wf in [0,129).
// grid = nimg*128 blocks, 128 threads.
// ---------------------------------------------------------------------------
__global__ void rfft_rows_kernel(const float* __restrict__ in,
                                 float2* __restrict__ outf) {
    __shared__ float2 z[256];
    __shared__ float2 tw[256];
    const int t = threadIdx.x;            // 0..127
    const int n = blockIdx.x >> 7;
    const int r = blockIdx.x & 127;       // row pair index
    tw[t]       = g_tw[t];
    tw[t + 128] = g_tw[t + 128];
    const float* rowA = in + ((size_t)n*HH + 2*r) * WW;   // rowB = rowA + WW
    z[t]       = make_float2(rowA[t],       rowA[WW + t]);
    z[t + 128] = make_float2(rowA[t + 128], rowA[WW + t + 128]);
    __syncthreads();
    fft256<0>(z, 1, t, 128, tw);
    // unpack: A[k] = (Z[k]+conj(Z[-k]))/2 ; B[k] = (Z[k]-conj(Z[-k]))/(2i)
    float2* oA = outf + ((size_t)n*HH + 2*r) * NWF;       // oB = oA + NWF
    for (int k = t; k <= 128; k += 128) {                 // t==0 also does k=128
        float2 Zk = z[k];
        float2 Zn = z[(256 - k) & 255];
        oA[k]       = make_float2(0.5f*(Zk.x + Zn.x), 0.5f*(Zk.y - Zn.y));
        oA[NWF + k] = make_float2(0.5f*(Zk.y + Zn.y), 0.5f*(Zn.x - Zk.x));
    }
}

// ---------------------------------------------------------------------------
// Complex FFT along H, in place, on (n, h, wf) layout. 8 columns per block.
// grid = nimg*17 blocks, 256 threads (32 threads per column FFT).
// INV=1 applies conjugate twiddles; 'scale' multiplied at store.
// ---------------------------------------------------------------------------
template<int INV>
__global__ void fft_cols_kernel(float2* __restrict__ data, float scale) {
    __shared__ float2 s[256*9];           // 8 cols, padded stride 9
    __shared__ float2 tw[256];
    const int t  = threadIdx.x;           // 0..255
    const int n  = blockIdx.x / 17;
    const int c0 = (blockIdx.x % 17) * 8;
    tw[t] = g_tw[t];
    float2* img = data + (size_t)n * FREQ;
    const int ncol = (NWF - c0 < 8) ? (NWF - c0) : 8;
    #pragma unroll
    for (int q = 0; q < 8; q++) {
        int idx = t + q*256;
        int h = idx >> 3, c = idx & 7;
        s[h*9 + c] = (c < ncol) ? img[h*NWF + c0 + c] : make_float2(0.f, 0.f);
    }
    __syncthreads();
    fft256<INV>(s + (t & 7), 9, t >> 3, 32, tw);
    #pragma unroll
    for (int q = 0; q < 8; q++) {
        int idx = t + q*256;
        int h = idx >> 3, c = idx & 7;
        if (c < ncol) {
            float2 v = s[h*9 + c];
            img[h*NWF + c0 + c] = make_float2(v.x*scale, v.y*scale);
        }
    }
}

// ---------------------------------------------------------------------------
// Per-bin channel contraction: Of[b,o,f] = sum_c Xf[b,c,f] * Kf[o,c,f]
// grid = (FREQ/32, NB/8), 256 threads. 32 bins x 8 b-rows x 32 o per block.
// Each thread owns one f and 8b x 4o accumulators (64 fp32 regs).
// ---------------------------------------------------------------------------
__global__ void einsum_kernel(const float2* __restrict__ Xf,
                              const float2* __restrict__ Kf,
                              float2* __restrict__ Of) {
    __shared__ float2 Xs[8*32];           // [b][f]
    __shared__ float2 Ks[32*32];          // [o][f]
    const int t    = threadIdx.x;         // 0..255
    const int f0   = blockIdx.x * 32;
    const int b0   = blockIdx.y * 8;
    const int f    = t & 31;
    const int slot = t >> 5;              // 0..7
    float2 acc[8][4];
    #pragma unroll
    for (int b = 0; b < 8; b++)
        #pragma unroll
        for (int q = 0; q < 4; q++) acc[b][q] = make_float2(0.f, 0.f);

    for (int c = 0; c < NC; c++) {
        __syncthreads();
        {   // X tile: 8 b-rows x 32 bins, one float2 per thread, coalesced
            int b = t >> 5, fl = t & 31;
            Xs[b*32 + fl] = Xf[((size_t)(b0 + b)*NC + c)*FREQ + f0 + fl];
        }
        #pragma unroll
        for (int q = 0; q < 4; q++) {     // K tile: 32 o-rows x 32 bins
            int idx = t + q*256;
            int o = idx >> 5, fl = idx & 31;
            Ks[o*32 + fl] = Kf[((size_t)o*NC + c)*FREQ + f0 + fl];
        }
        __syncthreads();
        float2 xv[8], kv[4];
        #pragma unroll
        for (int b = 0; b < 8; b++) xv[b] = Xs[b*32 + f];
        #pragma unroll
        for (int q = 0; q < 4; q++) kv[q] = Ks[(slot + 8*q)*32 + f];
        #pragma unroll
        for (int b = 0; b < 8; b++)
            #pragma unroll
            for (int q = 0; q < 4; q++) {
                acc[b][q].x = fmaf(xv[b].x, kv[q].x,
                              fmaf(-xv[b].y, kv[q].y, acc[b][q].x));
                acc[b][q].y = fmaf(xv[b].x, kv[q].y,
                              fmaf( xv[b].y, kv[q].x, acc[b][q].y));
            }
    }
    #pragma unroll
    for (int b = 0; b < 8; b++)
        #pragma unroll
        for (int q = 0; q < 4; q++) {
            int o = slot + 8*q;
            Of[((size_t)(b0 + b)*NO + o)*FREQ + f0 + f] = acc[b][q];
        }
}

// ---------------------------------------------------------------------------
// Inverse real FFT along W, two output rows per complex IFFT.
// Z[k] = A[k] + i*B[k] (conjugate-symmetric extension), IFFT -> a=Re, b=Im.
// grid = nimg*128 blocks, 128 threads. Applies final 1/256.
// ---------------------------------------------------------------------------
__global__ void irfft_rows_kernel(const float2* __restrict__ inf,
                                  float* __restrict__ out) {
    __shared__ float2 z[256];
    __shared__ float2 tw[256];
    const int t = threadIdx.x;            // 0..127
    const int n = blockIdx.x >> 7;
    const int r = blockIdx.x & 127;
    tw[t]       = g_tw[t];
    tw[t + 128] = g_tw[t + 128];
    const float2* iA = inf + ((size_t)n*HH + 2*r) * NWF;  // iB = iA + NWF
    for (int k = t; k <= 128; k += 128) {
        float2 A  = iA[k];
        float2 Bv = iA[NWF + k];
        z[k] = make_float2(A.x - Bv.y, A.y + Bv.x);
        if (k > 0 && k < 128)
            z[256 - k] = make_float2(A.x + Bv.y, Bv.x - A.y);
    }
    __syncthreads();
    fft256<1>(z, 1, t, 128, tw);
    float* oA = out + ((size_t)n*HH + 2*r) * WW;          // oB = oA + WW
    const float sc = 1.0f/256.0f;
    oA[t]            = z[t].x * sc;
    oA[t + 128]      = z[t + 128].x * sc;
    oA[WW + t]       = z[t].y * sc;
    oA[WW + t + 128] = z[t + 128].y * sc;
}

// ---------------------------------------------------------------------------
extern "C" void kernel_launch(void* const* d_in, const int* in_sizes, int n_in,
                              void* d_out, int out_size) {
    const float* x = (const float*)d_in[0];   // (16,32,256,256)
    const float* w = (const float*)d_in[1];   // (32,32,256,256)
    float* out = (float*)d_out;               // (16,32,256,256)

    float2 *Xf, *Kf, *Of;
    cudaGetSymbolAddress((void**)&Xf, g_Xf);
    cudaGetSymbolAddress((void**)&Kf, g_Kf);
    cudaGetSymbolAddress((void**)&Of, g_Of);

    init_tw_kernel<<<1, 256>>>();

    // forward FFTs
    rfft_rows_kernel<<<NB*NC*(HH/2), 128>>>(x, Xf);       // 65536 blocks
    rfft_rows_kernel<<<NO*NC*(HH/2), 128>>>(w, Kf);       // 131072 blocks
    fft_cols_kernel<0><<<NB*NC*17, 256>>>(Xf, 1.0f);
    fft_cols_kernel<0><<<NO*NC*17, 256>>>(Kf, 1.0f);

    // frequency-domain channel contraction
    einsum_kernel<<<dim3(FREQ/32, NB/8), 256>>>(Xf, Kf, Of);

    // inverse FFTs (1/256 here, 1/256 in irfft_rows -> total 1/65536)
    fft_cols_kernel<1><<<NB*NO*17, 256>>>(Of, 1.0f/256.0f);
    irfft_rows_kernel<<<NB*NO*(HH/2), 128>>>(Of, out);
}

// round 2
// speedup vs baseline: 1.7067x; 1.7067x over previous
#include <cuda_runtime.h>
#include <cstdint>

// Problem dims (fixed by the dataset)
#define HH   256
#define WW   256
#define NWF  129                 // W/2+1
#define FREQ (HH*NWF)            // 33024 frequency bins
#define NB   16                  // batch
#define NC   32                  // in channels
#define NO   32                  // out channels

// Frequency-domain scratch (static device globals: allocation-free)
__device__ float2 g_Xf[NB*NC*FREQ];   // 135 MB
__device__ float2 g_Kf[NO*NC*FREQ];   // 270 MB
__device__ float2 g_Of[NB*NO*FREQ];   // 135 MB
__device__ float2 g_tw[256];          // forward twiddles e^{-2pi i k/256}

// ---------------------------------------------------------------------------
__global__ void init_tw_kernel() {
    int k = threadIdx.x;
    double s, c;
    sincospi((double)k / 128.0, &s, &c);   // angle = 2*pi*k/256
    g_tw[k] = make_float2((float)c, (float)(-s));
}

// ---------------------------------------------------------------------------
// complex helpers
// ---------------------------------------------------------------------------
__device__ __forceinline__ float2 cadd(float2 a, float2 b) {
    return make_float2(a.x + b.x, a.y + b.y);
}
__device__ __forceinline__ float2 csub(float2 a, float2 b) {
    return make_float2(a.x - b.x, a.y - b.y);
}
__device__ __forceinline__ float2 cmul(float2 a, float2 b) {
    return make_float2(a.x*b.x - a.y*b.y, a.x*b.y + a.y*b.x);
}
// multiply by -i (forward) or +i (inverse)
template<int INV>
__device__ __forceinline__ float2 mul_mi(float2 a) {
    return INV ? make_float2(-a.y, a.x) : make_float2(a.y, -a.x);
}

// ---------------------------------------------------------------------------
// 8-point DFT in registers, natural order in and out.
// ---------------------------------------------------------------------------
template<int INV>
__device__ __forceinline__ void fft8(float2 a[8]) {
    // FFT4 over evens (a0,a2,a4,a6)
    float2 s0 = cadd(a[0], a[4]), d0 = csub(a[0], a[4]);
    float2 s1 = cadd(a[2], a[6]), d1 = csub(a[2], a[6]);
    float2 e0 = cadd(s0, s1);
    float2 e2 = csub(s0, s1);
    float2 d1i = mul_mi<INV>(d1);
    float2 e1 = cadd(d0, d1i);
    float2 e3 = csub(d0, d1i);
    // FFT4 over odds (a1,a3,a5,a7)
    float2 t0 = cadd(a[1], a[5]), u0 = csub(a[1], a[5]);
    float2 t1 = cadd(a[3], a[7]), u1 = csub(a[3], a[7]);
    float2 o0 = cadd(t0, t1);
    float2 o2 = csub(t0, t1);
    float2 u1i = mul_mi<INV>(u1);
    float2 o1 = cadd(u0, u1i);
    float2 o3 = csub(u0, u1i);
    const float s = 0.70710678118654752f;
    // W8^1: fwd (s,-s)  inv (s,s)
    float2 w1o1 = INV ? make_float2(s*(o1.x - o1.y), s*(o1.y + o1.x))
                      : make_float2(s*(o1.x + o1.y), s*(o1.y - o1.x));
    float2 w2o2 = mul_mi<INV>(o2);
    // W8^3: fwd (-s,-s)  inv (-s,s)
    float2 w3o3 = INV ? make_float2(s*(-o3.x - o3.y), s*( o3.x - o3.y))
                      : make_float2(s*(-o3.x + o3.y), s*(-o3.x - o3.y));
    a[0] = cadd(e0, o0);   a[4] = csub(e0, o0);
    a[1] = cadd(e1, w1o1); a[5] = csub(e1, w1o1);
    a[2] = cadd(e2, w2o2); a[6] = csub(e2, w2o2);
    a[3] = cadd(e3, w3o3); a[7] = csub(e3, w3o3);
}

// ---------------------------------------------------------------------------
// Warp-cooperative 256-point FFT. Entry: a[n1] = x[32*n1 + lane].
// Exit:  a[k1] = X[8*brev5(lane) + k1].
// tw: shared table of forward twiddles W_256^k.
// ---------------------------------------------------------------------------
template<int INV>
__device__ __forceinline__ void warp_fft256(float2 a[8], int lane,
                                            const float2* tw) {
    fft8<INV>(a);
    // twiddle by W_256^{lane*k1}
    #pragma unroll
    for (int k1 = 1; k1 < 8; k1++) {
        float2 w = tw[lane * k1];
        if (INV) w.y = -w.y;
        a[k1] = cmul(a[k1], w);
    }
    // 32-point DIF across lanes (shfl_xor), 5 stages h = 16..1
    #pragma unroll
    for (int st = 0; st < 5; st++) {
        const int h = 16 >> st;
        int j = lane & (h - 1);
        float2 w = tw[j * (128 / h)];
        if (INV) w.y = -w.y;
        bool upper = (lane & h) != 0;
        #pragma unroll
        for (int r = 0; r < 8; r++) {
            float px = __shfl_xor_sync(0xffffffffu, a[r].x, h);
            float py = __shfl_xor_sync(0xffffffffu, a[r].y, h);
            if (upper) {
                float2 d = make_float2(px - a[r].x, py - a[r].y);
                a[r] = (h == 1) ? d : cmul(d, w);
            } else {
                a[r].x += px;
                a[r].y += py;
            }
        }
    }
}

// ---------------------------------------------------------------------------
// Forward real FFT along W, two rows per complex FFT, one warp per row-pair.
// grid = nimg*16 blocks, 256 threads (8 warps).
// ---------------------------------------------------------------------------
__global__ void rfft_rows_kernel(const float* __restrict__ in,
                                 float2* __restrict__ outf) {
    __shared__ float2 sz[8*264];          // per-warp 264 (33*8)
    __shared__ float2 tw[256];
    const int t = threadIdx.x, w = t >> 5, lane = t & 31;
    tw[t] = g_tw[t];
    const int rp = blockIdx.x * 8 + w;    // global row-pair
    const int n = rp >> 7, r = rp & 127;
    const float* rowA = in + ((size_t)n*HH + 2*r) * WW;  // rowB = rowA+WW
    float2 a[8];
    #pragma unroll
    for (int n1 = 0; n1 < 8; n1++) {
        int i = 32*n1 + lane;
        a[n1] = make_float2(rowA[i], rowA[WW + i]);
    }
    __syncthreads();                      // tw ready
    warp_fft256<0>(a, lane, tw);
    float2* S = sz + w * 264;             // S[(k&7)*33 + (k>>3)]
    const int kr = __brev(lane) >> 27;
    #pragma unroll
    for (int k1 = 0; k1 < 8; k1++)
        S[k1*33 + kr] = a[k1];            // k = 8*kr+k1 -> (k&7)=k1,(k>>3)=kr
    __syncwarp();
    // unpack: A[k] = (Z[k]+conj(Z[-k]))/2 ; B[k] = (Z[k]-conj(Z[-k]))/(2i)
    float2* oA = outf + ((size_t)n*HH + 2*r) * NWF;      // oB = oA + NWF
    #pragma unroll
    for (int m = 0; m < 4; m++) {
        int k  = lane + 32*m;
        int kn = (256 - k) & 255;
        float2 Zk = S[(k  & 7)*33 + (k  >> 3)];
        float2 Zn = S[(kn & 7)*33 + (kn >> 3)];
        oA[k]       = make_float2(0.5f*(Zk.x + Zn.x), 0.5f*(Zk.y - Zn.y));
        oA[NWF + k] = make_float2(0.5f*(Zk.y + Zn.y), 0.5f*(Zn.x - Zk.x));
    }
    if (lane == 0) {                      // k = 128 (Zn = Zk)
        float2 Zk = S[0*33 + 16];
        oA[128]       = make_float2(Zk.x, 0.f);
        oA[NWF + 128] = make_float2(Zk.y, 0.f);
    }
}

// ---------------------------------------------------------------------------
// Complex FFT along H, in place. 8 columns per block, one warp per column.
// grid = nimg*17 blocks, 256 threads.
// ---------------------------------------------------------------------------
template<int INV>
__global__ void fft_cols_kernel(float2* __restrict__ data, float scale) {
    __shared__ float2 s[256*9];           // [h][col], stride 9
    __shared__ float2 tw[256];
    const int t  = threadIdx.x;
    const int n  = blockIdx.x / 17;
    const int c0 = (blockIdx.x % 17) * 8;
    tw[t] = g_tw[t];
    float2* img = data + (size_t)n * FREQ;
    const int ncol = (NWF - c0 < 8) ? (NWF - c0) : 8;
    #pragma unroll
    for (int q = 0; q < 8; q++) {
        int idx = t + q*256, h = idx >> 3, c = idx & 7;
        s[h*9 + c] = (c < ncol) ? img[h*NWF + c0 + c] : make_float2(0.f, 0.f);
    }
    __syncthreads();
    const int w = t >> 5, lane = t & 31;
    float2 a[8];
    #pragma unroll
    for (int n1 = 0; n1 < 8; n1++)
        a[n1] = s[(32*n1 + lane)*9 + w];
    warp_fft256<INV>(a, lane, tw);
    const int kr = __brev(lane) >> 27;
    __syncwarp();                         // column w reads done (warp-local)
    #pragma unroll
    for (int k1 = 0; k1 < 8; k1++) {
        float2 v = a[k1];
        s[(8*kr + k1)*9 + w] = make_float2(v.x*scale, v.y*scale);
    }
    __syncthreads();
    #pragma unroll
    for (int q = 0; q < 8; q++) {
        int idx = t + q*256, h = idx >> 3, c = idx & 7;
        if (c < ncol) img[h*NWF + c0 + c] = s[h*9 + c];
    }
}

// ---------------------------------------------------------------------------
// f32x2 packed FMA helpers (Blackwell FFMA2 via PTX)
// ---------------------------------------------------------------------------
__device__ __forceinline__ unsigned long long pk2(float lo, float hi) {
    unsigned long long r;
    asm("mov.b64 %0, {%1, %2};" : "=l"(r)
        : "r"(__float_as_uint(lo)), "r"(__float_as_uint(hi)));
    return r;
}
__device__ __forceinline__ void fma2(unsigned long long& d,
                                     unsigned long long a,
                                     unsigned long long b) {
    asm("fma.rn.f32x2 %0, %1, %2, %3;" : "=l"(d) : "l"(a), "l"(b), "l"(d));
}
__device__ __forceinline__ float2 upk2(unsigned long long v) {
    unsigned int lo, hi;
    asm("mov.b64 {%0, %1}, %2;" : "=r"(lo), "=r"(hi) : "l"(v));
    return make_float2(__uint_as_float(lo), __uint_as_float(hi));
}

// ---------------------------------------------------------------------------
// Per-bin channel contraction: Of[b,o,f] = sum_c Xf[b,c,f] * Kf[o,c,f]
// grid = (FREQ/32, NB/8), 256 threads. 32 bins x 8 b-rows x 32 o per block.
// ---------------------------------------------------------------------------
__global__ void einsum_kernel(const float2* __restrict__ Xf,
                              const float2* __restrict__ Kf,
                              float2* __restrict__ Of) {
    __shared__ float2 Xs[8*32];           // [b][f]
    __shared__ float2 Ks[32*32];          // [o][f]
    const int t    = threadIdx.x;
    const int f0   = blockIdx.x * 32;
    const int b0   = blockIdx.y * 8;
    const int f    = t & 31;
    const int slot = t >> 5;              // 0..7
    unsigned long long acc[8][4];
    #pragma unroll
    for (int b = 0; b < 8; b++)
        #pragma unroll
        for (int q = 0; q < 4; q++) acc[b][q] = 0ull;

    for (int c = 0; c < NC; c++) {
        __syncthreads();
        {
            int b = t >> 5, fl = t & 31;
            Xs[b*32 + fl] = Xf[((size_t)(b0 + b)*NC + c)*FREQ + f0 + fl];
        }
        #pragma unroll
        for (int q = 0; q < 4; q++) {
            int idx = t + q*256;
            int o = idx >> 5, fl = idx & 31;
            Ks[o*32 + fl] = Kf[((size_t)o*NC + c)*FREQ + f0 + fl];
        }
        __syncthreads();
        unsigned long long pxx[8], pmx[8], pk[4], pks[4];
        #pragma unroll
        for (int b = 0; b < 8; b++) {
            float2 xv = Xs[b*32 + f];
            pxx[b] = pk2(xv.x, xv.x);
            pmx[b] = pk2(-xv.y, xv.y);
        }
        #pragma unroll
        for (int q = 0; q < 4; q++) {
            float2 kv = Ks[(slot + 8*q)*32 + f];
            pk[q]  = pk2(kv.x, kv.y);
            pks[q] = pk2(kv.y, kv.x);
        }
        #pragma unroll
        for (int b = 0; b < 8; b++)
            #pragma unroll
            for (int q = 0; q < 4; q++) {
                fma2(acc[b][q], pxx[b], pk[q]);   // (+xr*kr, +xr*ki)
                fma2(acc[b][q], pmx[b], pks[q]);  // (-xi*ki, +xi*kr)
            }
    }
    #pragma unroll
    for (int b = 0; b < 8; b++)
        #pragma unroll
        for (int q = 0; q < 4; q++) {
            int o = slot + 8*q;
            Of[((size_t)(b0 + b)*NO + o)*FREQ + f0 + f] = upk2(acc[b][q]);
        }
}

// ---------------------------------------------------------------------------
// Inverse real FFT along W, two output rows per complex IFFT, warp per pair.
// grid = nimg*16 blocks, 256 threads. Applies final 1/256.
// ---------------------------------------------------------------------------
__global__ void irfft_rows_kernel(const float2* __restrict__ inf,
                                  float* __restrict__ out) {
    __shared__ float2 sz[8*264];
    __shared__ float2 tw[256];
    const int t = threadIdx.x, w = t >> 5, lane = t & 31;
    tw[t] = g_tw[t];
    const int rp = blockIdx.x * 8 + w;
    const int n = rp >> 7, r = rp & 127;
    const float2* iA = inf + ((size_t)n*HH + 2*r) * NWF;  // iB = iA + NWF
    float2* S = sz + w * 264;             // S[(k&7)*33 + (k>>3)]
    #pragma unroll
    for (int m = 0; m < 4; m++) {
        int k = lane + 32*m;
        float2 A  = iA[k];
        float2 Bv = iA[NWF + k];
        S[(k & 7)*33 + (k >> 3)] = make_float2(A.x - Bv.y, A.y + Bv.x);
        if (k > 0) {
            int kn = 256 - k;
            S[(kn & 7)*33 + (kn >> 3)] = make_float2(A.x + Bv.y, Bv.x - A.y);
        }
    }
    if (lane == 0) {                      // k = 128
        float2 A  = iA[128];
        float2 Bv = iA[NWF + 128];
        S[0*33 + 16] = make_float2(A.x - Bv.y, A.y + Bv.x);
    }
    __syncthreads();                      // tw ready (S is warp-local)
    float2 a[8];
    #pragma unroll
    for (int n1 = 0; n1 < 8; n1++) {
        int i = 32*n1 + lane;
        a[n1] = S[(i & 7)*33 + (i >> 3)];
    }
    warp_fft256<1>(a, lane, tw);
    const int kr = __brev(lane) >> 27;
    __syncwarp();
    const float sc = 1.0f/256.0f;
    #pragma unroll
    for (int k1 = 0; k1 < 8; k1++) {      // time idx = 8*kr+k1
        float2 v = a[k1];
        S[k1*33 + kr] = make_float2(v.x*sc, v.y*sc);
    }
    __syncwarp();
    float* oA = out + ((size_t)n*HH + 2*r) * WW;          // oB = oA + WW
    #pragma unroll
    for (int m = 0; m < 8; m++) {
        int i = lane + 32*m;
        float2 v = S[(i & 7)*33 + (i >> 3)];
        oA[i]      = v.x;
        oA[WW + i] = v.y;
    }
}

// ---------------------------------------------------------------------------
extern "C" void kernel_launch(void* const* d_in, const int* in_sizes, int n_in,
                              void* d_out, int out_size) {
    const float* x = (const float*)d_in[0];   // (16,32,256,256)
    const float* w = (const float*)d_in[1];   // (32,32,256,256)
    float* out = (float*)d_out;               // (16,32,256,256)

    float2 *Xf, *Kf, *Of;
    cudaGetSymbolAddress((void**)&Xf, g_Xf);
    cudaGetSymbolAddress((void**)&Kf, g_Kf);
    cudaGetSymbolAddress((void**)&Of, g_Of);

    init_tw_kernel<<<1, 256>>>();

    // forward FFTs
    rfft_rows_kernel<<<NB*NC*16, 256>>>(x, Xf);
    rfft_rows_kernel<<<NO*NC*16, 256>>>(w, Kf);
    fft_cols_kernel<0><<<NB*NC*17, 256>>>(Xf, 1.0f);
    fft_cols_kernel<0><<<NO*NC*17, 256>>>(Kf, 1.0f);

    // frequency-domain channel contraction
    einsum_kernel<<<dim3(FREQ/32, NB/8), 256>>>(Xf, Kf, Of);

    // inverse FFTs (1/256 here, 1/256 in irfft_rows -> total 1/65536)
    fft_cols_kernel<1><<<NB*NO*17, 256>>>(Of, 1.0f/256.0f);
    irfft_rows_kernel<<<NB*NO*16, 256>>>(Of, out);
}